// round 1
// baseline (speedup 1.0000x reference)
#include <cuda_runtime.h>
#include <math.h>

#define Nn 10000
#define Hh 512
#define Tt 4
#define Ee 40000
#define Ll 2
#define G3 (3*Hh)

#define BM 128
#define BN 128
#define BK 16

// ---------------- device scratch (static: no runtime allocation) ----------------
__device__ __align__(16) float g_S  [(size_t)Tt*Nn*Hh];   // 81.9 MB  per-(type,target) summed src states
__device__ __align__(16) float g_h  [2*(size_t)Nn*Hh];    // 41 MB    ping-pong hidden state
__device__ __align__(16) float g_inc[(size_t)Nn*Hh];      // 20.5 MB  incoming messages
__device__ __align__(16) float g_gi [(size_t)Nn*G3];      // 61.4 MB  input gates (also reused as fc out)
__device__ __align__(16) float g_gh [(size_t)Nn*G3];      // 61.4 MB  hidden gates
__device__ __align__(16) float g_pm [100*Hh];             // partial max
__device__ int g_deg[Tt*Nn];                              // in-degree per (type, node)

// ---------------- utility kernels ----------------
__global__ void zero_f4(float4* p, int n4) {
    int i = blockIdx.x * blockDim.x + threadIdx.x;
    int stride = gridDim.x * blockDim.x;
    float4 z = make_float4(0.f, 0.f, 0.f, 0.f);
    for (; i < n4; i += stride) p[i] = z;
}

__global__ void copy_f4(const float4* __restrict__ s, float4* __restrict__ d, int n4) {
    int i = blockIdx.x * blockDim.x + threadIdx.x;
    int stride = gridDim.x * blockDim.x;
    for (; i < n4; i += stride) d[i] = s[i];
}

__global__ void zero_i(int* p, int n) {
    int i = blockIdx.x * blockDim.x + threadIdx.x;
    if (i < n) p[i] = 0;
}

__global__ void count_deg(const int* __restrict__ edges, int* __restrict__ deg) {
    int idx = blockIdx.x * blockDim.x + threadIdx.x;
    if (idx < Tt * Ee) {
        int t = idx / Ee;
        int tgt = edges[idx * 2 + 1];
        atomicAdd(&deg[t * Nn + tgt], 1);
    }
}

// ---------------- aggregation: S[t][tgt] += h[src] for every edge ----------------
// one warp per edge; h row (2KB) gathered as float4, scalar atomics into S
__global__ void aggregate_kernel(const float* __restrict__ h,
                                 const int* __restrict__ edges,
                                 float* __restrict__ S) {
    int warp = (blockIdx.x * blockDim.x + threadIdx.x) >> 5;
    int lane = threadIdx.x & 31;
    if (warp >= Tt * Ee) return;
    int t   = warp / Ee;
    int src = edges[warp * 2 + 0];
    int tgt = edges[warp * 2 + 1];
    const float4* srow = reinterpret_cast<const float4*>(h + (size_t)src * Hh);
    float* drow = S + ((size_t)t * Nn + tgt) * Hh;
#pragma unroll
    for (int i = 0; i < 4; i++) {
        float4 v = srow[i * 32 + lane];
        int off = (i * 32 + lane) * 4;
        atomicAdd(drow + off + 0, v.x);
        atomicAdd(drow + off + 1, v.y);
        atomicAdd(drow + off + 2, v.z);
        atomicAdd(drow + off + 3, v.w);
    }
}

// ---------------- generic SGEMM: C[M,Nout] = A[M,512] * B[Nout,512]^T + bias ----------------
__global__ __launch_bounds__(256)
void sgemm_abt(const float* __restrict__ A, const float* __restrict__ B,
               const float* __restrict__ bias, float* __restrict__ C,
               int M, int Nout) {
    __shared__ float As[BK][BM];
    __shared__ float Bs[BK][BN];
    const int K = Hh;
    int m0 = blockIdx.x * BM;
    int n0 = blockIdx.y * BN;
    int tid = threadIdx.x;
    int tx = tid & 15, ty = tid >> 4;
    float acc[8][8] = {};

    for (int k0 = 0; k0 < K; k0 += BK) {
#pragma unroll
        for (int j = 0; j < 2; j++) {
            int slot = tid * 2 + j;          // 0..511
            int r  = slot >> 2;              // 0..127
            int c4 = slot & 3;               // 0..3
            int m = m0 + r;
            float4 v = make_float4(0.f, 0.f, 0.f, 0.f);
            if (m < M) v = *reinterpret_cast<const float4*>(A + (size_t)m * K + k0 + c4 * 4);
            As[c4*4+0][r] = v.x; As[c4*4+1][r] = v.y;
            As[c4*4+2][r] = v.z; As[c4*4+3][r] = v.w;
        }
#pragma unroll
        for (int j = 0; j < 2; j++) {
            int slot = tid * 2 + j;
            int r  = slot >> 2;
            int c4 = slot & 3;
            float4 v = *reinterpret_cast<const float4*>(B + (size_t)(n0 + r) * K + k0 + c4 * 4);
            Bs[c4*4+0][r] = v.x; Bs[c4*4+1][r] = v.y;
            Bs[c4*4+2][r] = v.z; Bs[c4*4+3][r] = v.w;
        }
        __syncthreads();
#pragma unroll
        for (int kk = 0; kk < BK; kk++) {
            float a[8], b[8];
#pragma unroll
            for (int i = 0; i < 8; i += 4)
                *reinterpret_cast<float4*>(a + i) = *reinterpret_cast<const float4*>(&As[kk][ty * 8 + i]);
#pragma unroll
            for (int i = 0; i < 8; i += 4)
                *reinterpret_cast<float4*>(b + i) = *reinterpret_cast<const float4*>(&Bs[kk][tx * 8 + i]);
#pragma unroll
            for (int i = 0; i < 8; i++)
#pragma unroll
                for (int jj = 0; jj < 8; jj++)
                    acc[i][jj] = fmaf(a[i], b[jj], acc[i][jj]);
        }
        __syncthreads();
    }

#pragma unroll
    for (int i = 0; i < 8; i++) {
        int m = m0 + ty * 8 + i;
        if (m >= M) break;
#pragma unroll
        for (int jj = 0; jj < 8; jj++) {
            int n = n0 + tx * 8 + jj;
            C[(size_t)m * Nout + n] = acc[i][jj] + bias[n];
        }
    }
}

// ---------------- message GEMM: incoming = Σ_t S_t * W_msg[t]^T + deg_t * b_msg[t] ----------------
__global__ __launch_bounds__(256)
void msg_gemm(const float* __restrict__ S, const float* __restrict__ Wm,
              const float* __restrict__ bm, const int* __restrict__ deg,
              float* __restrict__ C) {
    __shared__ float As[BK][BM];
    __shared__ float Bs[BK][BN];
    int m0 = blockIdx.x * BM;
    int n0 = blockIdx.y * BN;
    int tid = threadIdx.x;
    int tx = tid & 15, ty = tid >> 4;
    float acc[8][8] = {};

    for (int k0 = 0; k0 < Tt * Hh; k0 += BK) {
        int t  = k0 >> 9;
        int kb = k0 & (Hh - 1);
        const float* At = S  + (size_t)t * Nn * Hh;
        const float* Bt = Wm + (size_t)t * Hh * Hh;
#pragma unroll
        for (int j = 0; j < 2; j++) {
            int slot = tid * 2 + j;
            int r  = slot >> 2;
            int c4 = slot & 3;
            int m = m0 + r;
            float4 v = make_float4(0.f, 0.f, 0.f, 0.f);
            if (m < Nn) v = *reinterpret_cast<const float4*>(At + (size_t)m * Hh + kb + c4 * 4);
            As[c4*4+0][r] = v.x; As[c4*4+1][r] = v.y;
            As[c4*4+2][r] = v.z; As[c4*4+3][r] = v.w;
        }
#pragma unroll
        for (int j = 0; j < 2; j++) {
            int slot = tid * 2 + j;
            int r  = slot >> 2;
            int c4 = slot & 3;
            float4 v = *reinterpret_cast<const float4*>(Bt + (size_t)(n0 + r) * Hh + kb + c4 * 4);
            Bs[c4*4+0][r] = v.x; Bs[c4*4+1][r] = v.y;
            Bs[c4*4+2][r] = v.z; Bs[c4*4+3][r] = v.w;
        }
        __syncthreads();
#pragma unroll
        for (int kk = 0; kk < BK; kk++) {
            float a[8], b[8];
#pragma unroll
            for (int i = 0; i < 8; i += 4)
                *reinterpret_cast<float4*>(a + i) = *reinterpret_cast<const float4*>(&As[kk][ty * 8 + i]);
#pragma unroll
            for (int i = 0; i < 8; i += 4)
                *reinterpret_cast<float4*>(b + i) = *reinterpret_cast<const float4*>(&Bs[kk][tx * 8 + i]);
#pragma unroll
            for (int i = 0; i < 8; i++)
#pragma unroll
                for (int jj = 0; jj < 8; jj++)
                    acc[i][jj] = fmaf(a[i], b[jj], acc[i][jj]);
        }
        __syncthreads();
    }

    // epilogue: + Σ_t deg[t][m] * b_msg[t][n]
    float bcol[Tt][8];
#pragma unroll
    for (int t = 0; t < Tt; t++)
#pragma unroll
        for (int jj = 0; jj < 8; jj++)
            bcol[t][jj] = bm[t * Hh + n0 + tx * 8 + jj];

#pragma unroll
    for (int i = 0; i < 8; i++) {
        int m = m0 + ty * 8 + i;
        if (m >= Nn) break;
        float dg[Tt];
#pragma unroll
        for (int t = 0; t < Tt; t++) dg[t] = (float)deg[t * Nn + m];
#pragma unroll
        for (int jj = 0; jj < 8; jj++) {
            float v = acc[i][jj];
#pragma unroll
            for (int t = 0; t < Tt; t++) v += dg[t] * bcol[t][jj];
            C[(size_t)m * Hh + n0 + tx * 8 + jj] = v;
        }
    }
}

// ---------------- GRU elementwise ----------------
__global__ void gru_kernel(const float* __restrict__ gi, const float* __restrict__ gh,
                           const float* __restrict__ h, float* __restrict__ hout) {
    int idx = blockIdx.x * blockDim.x + threadIdx.x;
    if (idx >= Nn * Hh) return;
    int n = idx / Hh;
    int j = idx - n * Hh;
    size_t base = (size_t)n * G3 + j;
    float ir = gi[base],          hr = gh[base];
    float iz = gi[base + Hh],     hz = gh[base + Hh];
    float in_ = gi[base + 2*Hh],  hn = gh[base + 2*Hh];
    float r = 1.f / (1.f + expf(-(ir + hr)));
    float z = 1.f / (1.f + expf(-(iz + hz)));
    float nv = tanhf(in_ + r * hn);
    hout[idx] = (1.f - z) * nv + z * h[idx];
}

// ---------------- column max over nodes ----------------
__global__ void pmax_kernel(const float* __restrict__ X, float* __restrict__ pm) {
    int k = threadIdx.x;    // 512
    int b = blockIdx.x;     // 100 chunks of 100 rows
    float m = -INFINITY;
    int r0 = b * 100;
    for (int r = 0; r < 100; r++)
        m = fmaxf(m, X[(size_t)(r0 + r) * Hh + k]);
    pm[b * Hh + k] = m;
}

__global__ void fmax_kernel(const float* __restrict__ pm, float* __restrict__ out) {
    int k = threadIdx.x;    // 512
    float m = -INFINITY;
    for (int b = 0; b < 100; b++)
        m = fmaxf(m, pm[b * Hh + k]);
    out[k] = m;
}

// ---------------- launch ----------------
extern "C" void kernel_launch(void* const* d_in, const int* in_sizes, int n_in,
                              void* d_out, int out_size) {
    const float* x     = (const float*)d_in[0];
    const int*   edges = (const int*)  d_in[1];
    const float* W_msg = (const float*)d_in[2];
    const float* b_msg = (const float*)d_in[3];
    const float* W_ih  = (const float*)d_in[4];
    const float* W_hh  = (const float*)d_in[5];
    const float* b_ih  = (const float*)d_in[6];
    const float* b_hh  = (const float*)d_in[7];
    const float* fc_W  = (const float*)d_in[8];
    const float* fc_b  = (const float*)d_in[9];
    float* out = (float*)d_out;

    float *pS, *ph, *pinc, *pgi, *pgh, *ppm;
    int* pdeg;
    cudaGetSymbolAddress((void**)&pS,   g_S);
    cudaGetSymbolAddress((void**)&ph,   g_h);
    cudaGetSymbolAddress((void**)&pinc, g_inc);
    cudaGetSymbolAddress((void**)&pgi,  g_gi);
    cudaGetSymbolAddress((void**)&pgh,  g_gh);
    cudaGetSymbolAddress((void**)&ppm,  g_pm);
    cudaGetSymbolAddress((void**)&pdeg, g_deg);

    float* hc = ph;
    float* hn = ph + (size_t)Nn * Hh;

    // h = x
    copy_f4<<<2048, 256>>>((const float4*)x, (float4*)hc, Nn * Hh / 4);

    // in-degree per (type, node) — fixed across all steps
    zero_i<<<(Tt * Nn + 255) / 256, 256>>>(pdeg, Tt * Nn);
    count_deg<<<(Tt * Ee + 255) / 256, 256>>>(edges, pdeg);

    dim3 gm((Nn + BM - 1) / BM, Hh / BN);   // 79 x 4
    dim3 gg((Nn + BM - 1) / BM, G3 / BN);   // 79 x 12

    for (int layer = 0; layer < Ll; layer++) {
        const float* Wm_l  = W_msg + (size_t)layer * Tt * Hh * Hh;
        const float* bm_l  = b_msg + (size_t)layer * Tt * Hh;
        const float* Wih_l = W_ih  + (size_t)layer * G3 * Hh;
        const float* Whh_l = W_hh  + (size_t)layer * G3 * Hh;
        const float* bih_l = b_ih  + (size_t)layer * G3;
        const float* bhh_l = b_hh  + (size_t)layer * G3;
        for (int s = 0; s < 2; s++) {
            zero_f4<<<4096, 256>>>((float4*)pS, Tt * Nn * Hh / 4);
            aggregate_kernel<<<(Tt * Ee * 32 + 255) / 256, 256>>>(hc, edges, pS);
            msg_gemm<<<gm, 256>>>(pS, Wm_l, bm_l, pdeg, pinc);
            sgemm_abt<<<gg, 256>>>(pinc, Wih_l, bih_l, pgi, Nn, G3);
            sgemm_abt<<<gg, 256>>>(hc,   Whh_l, bhh_l, pgh, Nn, G3);
            gru_kernel<<<(Nn * Hh + 255) / 256, 256>>>(pgi, pgh, hc, hn);
            float* t = hc; hc = hn; hn = t;
        }
    }

    // out = h @ fc_W^T + fc_b, then graph_repr = max over nodes
    sgemm_abt<<<gm, 256>>>(hc, fc_W, fc_b, pgi, Nn, Hh);
    pmax_kernel<<<100, 512>>>(pgi, ppm);
    fmax_kernel<<<1, 512>>>(ppm, out);
}

// round 2
// speedup vs baseline: 1.1969x; 1.1969x over previous
#include <cuda_runtime.h>
#include <math.h>

#define Nn 10000
#define Hh 512
#define Tt 4
#define Ee 40000
#define Ll 2
#define G3 (3*Hh)

#define BM 128
#define BN 128
#define BK 16

typedef unsigned long long u64;

// ---------------- device scratch (static: no runtime allocation) ----------------
__device__ __align__(16) float g_S  [(size_t)Tt*Nn*Hh];
__device__ __align__(16) float g_h  [2*(size_t)Nn*Hh];
__device__ __align__(16) float g_inc[(size_t)Nn*Hh];
__device__ __align__(16) float g_gi [(size_t)Nn*G3];
__device__ __align__(16) float g_gh [(size_t)Nn*G3];
__device__ __align__(16) float g_pm [100*Hh];
__device__ int g_deg[Tt*Nn];

// ---------------- packed f32x2 helpers (Blackwell FFMA2) ----------------
__device__ __forceinline__ u64 pack_dup(float a) {
    u64 r;
    asm("mov.b64 %0, {%1, %1};" : "=l"(r) : "f"(a));
    return r;
}
__device__ __forceinline__ void fma2(u64& d, u64 a, u64 b) {
    asm("fma.rn.f32x2 %0, %1, %2, %0;" : "+l"(d) : "l"(a), "l"(b));
}
__device__ __forceinline__ void unpack2(u64 v, float& lo, float& hi) {
    asm("mov.b64 {%0, %1}, %2;" : "=f"(lo), "=f"(hi) : "l"(v));
}

// ---------------- utility kernels ----------------
__global__ void zero_f4(float4* p, int n4) {
    int i = blockIdx.x * blockDim.x + threadIdx.x;
    int stride = gridDim.x * blockDim.x;
    float4 z = make_float4(0.f, 0.f, 0.f, 0.f);
    for (; i < n4; i += stride) p[i] = z;
}

__global__ void copy_f4(const float4* __restrict__ s, float4* __restrict__ d, int n4) {
    int i = blockIdx.x * blockDim.x + threadIdx.x;
    int stride = gridDim.x * blockDim.x;
    for (; i < n4; i += stride) d[i] = s[i];
}

__global__ void zero_i(int* p, int n) {
    int i = blockIdx.x * blockDim.x + threadIdx.x;
    if (i < n) p[i] = 0;
}

__global__ void count_deg(const int* __restrict__ edges, int* __restrict__ deg) {
    int idx = blockIdx.x * blockDim.x + threadIdx.x;
    if (idx < Tt * Ee) {
        int t = idx / Ee;
        int tgt = edges[idx * 2 + 1];
        atomicAdd(&deg[t * Nn + tgt], 1);
    }
}

// ---------------- aggregation: S[t][tgt] += h[src], vector red.v4 ----------------
__global__ void aggregate_kernel(const float* __restrict__ h,
                                 const int* __restrict__ edges,
                                 float* __restrict__ S) {
    int warp = (blockIdx.x * blockDim.x + threadIdx.x) >> 5;
    int lane = threadIdx.x & 31;
    if (warp >= Tt * Ee) return;
    int t   = warp / Ee;
    int src = edges[warp * 2 + 0];
    int tgt = edges[warp * 2 + 1];
    const float4* srow = reinterpret_cast<const float4*>(h + (size_t)src * Hh);
    float* drow = S + ((size_t)t * Nn + tgt) * Hh;
#pragma unroll
    for (int i = 0; i < 4; i++) {
        float4 v = srow[i * 32 + lane];
        float* dst = drow + (i * 32 + lane) * 4;
        asm volatile("red.global.add.v4.f32 [%0], {%1, %2, %3, %4};"
                     :: "l"(dst), "f"(v.x), "f"(v.y), "f"(v.z), "f"(v.w)
                     : "memory");
    }
}

// ---------------- FFMA2 inner product core (shared by both GEMMs) ----------------
// As[BK][BM], Bs[BK][BN]; 256 threads, 8x8 output per thread (packed 8x4 pairs).
__device__ __forceinline__ void mma_tile_f32x2(
    const float (*As)[BM], const float (*Bs)[BN],
    int ty, int tx, u64 acc2[8][4])
{
#pragma unroll
    for (int kk = 0; kk < BK; kk++) {
        float a[8];
        *reinterpret_cast<float4*>(a)     = *reinterpret_cast<const float4*>(&As[kk][ty * 8]);
        *reinterpret_cast<float4*>(a + 4) = *reinterpret_cast<const float4*>(&As[kk][ty * 8 + 4]);
        u64 bp[4];
#pragma unroll
        for (int j = 0; j < 4; j++)
            bp[j] = *reinterpret_cast<const u64*>(&Bs[kk][tx * 8 + 2 * j]);
#pragma unroll
        for (int i = 0; i < 8; i++) {
            u64 ad = pack_dup(a[i]);
#pragma unroll
            for (int j = 0; j < 4; j++)
                fma2(acc2[i][j], ad, bp[j]);
        }
    }
}

// ---------------- generic SGEMM: C[M,Nout] = A[M,512] * B[Nout,512]^T + bias ----------------
__global__ __launch_bounds__(256)
void sgemm_abt(const float* __restrict__ A, const float* __restrict__ B,
               const float* __restrict__ bias, float* __restrict__ C,
               int M, int Nout) {
    __shared__ float As[BK][BM];
    __shared__ float Bs[BK][BN];
    const int K = Hh;
    int m0 = blockIdx.x * BM;
    int n0 = blockIdx.y * BN;
    int tid = threadIdx.x;
    int tx = tid & 15, ty = tid >> 4;
    u64 acc2[8][4] = {};

    for (int k0 = 0; k0 < K; k0 += BK) {
#pragma unroll
        for (int j = 0; j < 2; j++) {
            int slot = tid * 2 + j;
            int r  = slot >> 2;
            int c4 = slot & 3;
            int m = m0 + r;
            float4 v = make_float4(0.f, 0.f, 0.f, 0.f);
            if (m < M) v = *reinterpret_cast<const float4*>(A + (size_t)m * K + k0 + c4 * 4);
            As[c4*4+0][r] = v.x; As[c4*4+1][r] = v.y;
            As[c4*4+2][r] = v.z; As[c4*4+3][r] = v.w;
        }
#pragma unroll
        for (int j = 0; j < 2; j++) {
            int slot = tid * 2 + j;
            int r  = slot >> 2;
            int c4 = slot & 3;
            float4 v = *reinterpret_cast<const float4*>(B + (size_t)(n0 + r) * K + k0 + c4 * 4);
            Bs[c4*4+0][r] = v.x; Bs[c4*4+1][r] = v.y;
            Bs[c4*4+2][r] = v.z; Bs[c4*4+3][r] = v.w;
        }
        __syncthreads();
        mma_tile_f32x2(As, Bs, ty, tx, acc2);
        __syncthreads();
    }

#pragma unroll
    for (int i = 0; i < 8; i++) {
        int m = m0 + ty * 8 + i;
        if (m >= M) break;
#pragma unroll
        for (int j = 0; j < 4; j++) {
            int n = n0 + tx * 8 + 2 * j;
            float lo, hi;
            unpack2(acc2[i][j], lo, hi);
            float2 o = make_float2(lo + bias[n], hi + bias[n + 1]);
            *reinterpret_cast<float2*>(C + (size_t)m * Nout + n) = o;
        }
    }
}

// ---------------- message GEMM: incoming = Σ_t S_t * W_msg[t]^T + deg_t * b_msg[t] ----------------
__global__ __launch_bounds__(256)
void msg_gemm(const float* __restrict__ S, const float* __restrict__ Wm,
              const float* __restrict__ bm, const int* __restrict__ deg,
              float* __restrict__ C) {
    __shared__ float As[BK][BM];
    __shared__ float Bs[BK][BN];
    int m0 = blockIdx.x * BM;
    int n0 = blockIdx.y * BN;
    int tid = threadIdx.x;
    int tx = tid & 15, ty = tid >> 4;
    u64 acc2[8][4] = {};

    for (int k0 = 0; k0 < Tt * Hh; k0 += BK) {
        int t  = k0 >> 9;
        int kb = k0 & (Hh - 1);
        const float* At = S  + (size_t)t * Nn * Hh;
        const float* Bt = Wm + (size_t)t * Hh * Hh;
#pragma unroll
        for (int j = 0; j < 2; j++) {
            int slot = tid * 2 + j;
            int r  = slot >> 2;
            int c4 = slot & 3;
            int m = m0 + r;
            float4 v = make_float4(0.f, 0.f, 0.f, 0.f);
            if (m < Nn) v = *reinterpret_cast<const float4*>(At + (size_t)m * Hh + kb + c4 * 4);
            As[c4*4+0][r] = v.x; As[c4*4+1][r] = v.y;
            As[c4*4+2][r] = v.z; As[c4*4+3][r] = v.w;
        }
#pragma unroll
        for (int j = 0; j < 2; j++) {
            int slot = tid * 2 + j;
            int r  = slot >> 2;
            int c4 = slot & 3;
            float4 v = *reinterpret_cast<const float4*>(Bt + (size_t)(n0 + r) * Hh + kb + c4 * 4);
            Bs[c4*4+0][r] = v.x; Bs[c4*4+1][r] = v.y;
            Bs[c4*4+2][r] = v.z; Bs[c4*4+3][r] = v.w;
        }
        __syncthreads();
        mma_tile_f32x2(As, Bs, ty, tx, acc2);
        __syncthreads();
    }

    // epilogue: + Σ_t deg[t][m] * b_msg[t][n]
    float bcol[Tt][8];
#pragma unroll
    for (int t = 0; t < Tt; t++)
#pragma unroll
        for (int jj = 0; jj < 8; jj++)
            bcol[t][jj] = bm[t * Hh + n0 + tx * 8 + jj];

#pragma unroll
    for (int i = 0; i < 8; i++) {
        int m = m0 + ty * 8 + i;
        if (m >= Nn) break;
        float dg[Tt];
#pragma unroll
        for (int t = 0; t < Tt; t++) dg[t] = (float)deg[t * Nn + m];
#pragma unroll
        for (int j = 0; j < 4; j++) {
            float lo, hi;
            unpack2(acc2[i][j], lo, hi);
            float v0 = lo, v1 = hi;
#pragma unroll
            for (int t = 0; t < Tt; t++) {
                v0 += dg[t] * bcol[t][2 * j];
                v1 += dg[t] * bcol[t][2 * j + 1];
            }
            int n = n0 + tx * 8 + 2 * j;
            *reinterpret_cast<float2*>(C + (size_t)m * Hh + n) = make_float2(v0, v1);
        }
    }
}

// ---------------- GRU elementwise ----------------
__global__ void gru_kernel(const float* __restrict__ gi, const float* __restrict__ gh,
                           const float* __restrict__ h, float* __restrict__ hout) {
    int idx = blockIdx.x * blockDim.x + threadIdx.x;
    if (idx >= Nn * Hh) return;
    int n = idx / Hh;
    int j = idx - n * Hh;
    size_t base = (size_t)n * G3 + j;
    float ir = gi[base],          hr = gh[base];
    float iz = gi[base + Hh],     hz = gh[base + Hh];
    float in_ = gi[base + 2*Hh],  hn = gh[base + 2*Hh];
    float r = 1.f / (1.f + expf(-(ir + hr)));
    float z = 1.f / (1.f + expf(-(iz + hz)));
    float nv = tanhf(in_ + r * hn);
    hout[idx] = (1.f - z) * nv + z * h[idx];
}

// ---------------- column max over nodes ----------------
__global__ void pmax_kernel(const float* __restrict__ X, float* __restrict__ pm) {
    int k = threadIdx.x;
    int b = blockIdx.x;
    float m = -INFINITY;
    int r0 = b * 100;
    for (int r = 0; r < 100; r++)
        m = fmaxf(m, X[(size_t)(r0 + r) * Hh + k]);
    pm[b * Hh + k] = m;
}

__global__ void fmax_kernel(const float* __restrict__ pm, float* __restrict__ out) {
    int k = threadIdx.x;
    float m = -INFINITY;
    for (int b = 0; b < 100; b++)
        m = fmaxf(m, pm[b * Hh + k]);
    out[k] = m;
}

// ---------------- launch ----------------
extern "C" void kernel_launch(void* const* d_in, const int* in_sizes, int n_in,
                              void* d_out, int out_size) {
    const float* x     = (const float*)d_in[0];
    const int*   edges = (const int*)  d_in[1];
    const float* W_msg = (const float*)d_in[2];
    const float* b_msg = (const float*)d_in[3];
    const float* W_ih  = (const float*)d_in[4];
    const float* W_hh  = (const float*)d_in[5];
    const float* b_ih  = (const float*)d_in[6];
    const float* b_hh  = (const float*)d_in[7];
    const float* fc_W  = (const float*)d_in[8];
    const float* fc_b  = (const float*)d_in[9];
    float* out = (float*)d_out;

    float *pS, *ph, *pinc, *pgi, *pgh, *ppm;
    int* pdeg;
    cudaGetSymbolAddress((void**)&pS,   g_S);
    cudaGetSymbolAddress((void**)&ph,   g_h);
    cudaGetSymbolAddress((void**)&pinc, g_inc);
    cudaGetSymbolAddress((void**)&pgi,  g_gi);
    cudaGetSymbolAddress((void**)&pgh,  g_gh);
    cudaGetSymbolAddress((void**)&ppm,  g_pm);
    cudaGetSymbolAddress((void**)&pdeg, g_deg);

    float* hc = ph;
    float* hn = ph + (size_t)Nn * Hh;

    copy_f4<<<2048, 256>>>((const float4*)x, (float4*)hc, Nn * Hh / 4);
    zero_i<<<(Tt * Nn + 255) / 256, 256>>>(pdeg, Tt * Nn);
    count_deg<<<(Tt * Ee + 255) / 256, 256>>>(edges, pdeg);

    dim3 gm((Nn + BM - 1) / BM, Hh / BN);
    dim3 gg((Nn + BM - 1) / BM, G3 / BN);

    for (int layer = 0; layer < Ll; layer++) {
        const float* Wm_l  = W_msg + (size_t)layer * Tt * Hh * Hh;
        const float* bm_l  = b_msg + (size_t)layer * Tt * Hh;
        const float* Wih_l = W_ih  + (size_t)layer * G3 * Hh;
        const float* Whh_l = W_hh  + (size_t)layer * G3 * Hh;
        const float* bih_l = b_ih  + (size_t)layer * G3;
        const float* bhh_l = b_hh  + (size_t)layer * G3;
        for (int s = 0; s < 2; s++) {
            zero_f4<<<4096, 256>>>((float4*)pS, Tt * Nn * Hh / 4);
            aggregate_kernel<<<(Tt * Ee * 32 + 255) / 256, 256>>>(hc, edges, pS);
            msg_gemm<<<gm, 256>>>(pS, Wm_l, bm_l, pdeg, pinc);
            sgemm_abt<<<gg, 256>>>(pinc, Wih_l, bih_l, pgi, Nn, G3);
            sgemm_abt<<<gg, 256>>>(hc,   Whh_l, bhh_l, pgh, Nn, G3);
            gru_kernel<<<(Nn * Hh + 255) / 256, 256>>>(pgi, pgh, hc, hn);
            float* t = hc; hc = hn; hn = t;
        }
    }

    sgemm_abt<<<gm, 256>>>(hc, fc_W, fc_b, pgi, Nn, Hh);
    pmax_kernel<<<100, 512>>>(pgi, ppm);
    fmax_kernel<<<1, 512>>>(ppm, out);
}

// round 4
// speedup vs baseline: 2.2336x; 1.8662x over previous
#include <cuda_runtime.h>
#include <cuda_bf16.h>
#include <math.h>

#define Nn 10000
#define Hh 512
#define Tt 4
#define Ee 40000
#define Ll 2
#define G3 (3*Hh)

typedef unsigned long long u64;
typedef unsigned int u32;

// ---------------- device scratch ----------------
__device__ __align__(16) float g_S  [(size_t)Tt*Nn*Hh];
__device__ __align__(16) float g_h  [2*(size_t)Nn*Hh];
__device__ __align__(16) float g_inc[(size_t)Nn*Hh];
__device__ __align__(16) float g_gi [(size_t)Nn*G3];
__device__ __align__(16) float g_gh [(size_t)Nn*G3];
__device__ __align__(16) float g_pm [100*Hh];
__device__ int g_deg[Tt*Nn];

// ---------------- smem geometry ----------------
#define LDSB  80          // bytes per padded row (40 bf16, 32 used)
#define ATILE 10240       // 128 rows * 80 B
#define BUFSZ (4*ATILE)   // A_hi A_lo B_hi B_lo
#define SMEM_BYTES (2*BUFSZ)

__device__ __forceinline__ u32 smem_u32(const void* p) {
    u32 a;
    asm("{ .reg .u64 t; cvta.to.shared.u64 t, %1; cvt.u32.u64 %0, t; }" : "=r"(a) : "l"(p));
    return a;
}
__device__ __forceinline__ void ldsm4(u32 r[4], u32 addr) {
    asm volatile("ldmatrix.sync.aligned.m8n8.x4.shared.b16 {%0,%1,%2,%3}, [%4];"
                 : "=r"(r[0]), "=r"(r[1]), "=r"(r[2]), "=r"(r[3]) : "r"(addr));
}
__device__ __forceinline__ void mma16816(float d[4], const u32 a[4], u32 b0, u32 b1) {
    asm volatile("mma.sync.aligned.m16n8k16.row.col.f32.bf16.bf16.f32 "
                 "{%0,%1,%2,%3}, {%4,%5,%6,%7}, {%8,%9}, {%0,%1,%2,%3};"
                 : "+f"(d[0]), "+f"(d[1]), "+f"(d[2]), "+f"(d[3])
                 : "r"(a[0]), "r"(a[1]), "r"(a[2]), "r"(a[3]), "r"(b0), "r"(b1));
}
__device__ __forceinline__ void cvt4(float4 f, uint2& H, uint2& L) {
    float v[4] = {f.x, f.y, f.z, f.w};
    u32 hs[4], ls[4];
#pragma unroll
    for (int i = 0; i < 4; i++) {
        __nv_bfloat16 h = __float2bfloat16(v[i]);
        __nv_bfloat16 l = __float2bfloat16(v[i] - __bfloat162float(h));
        hs[i] = (u32)__bfloat16_as_ushort(h);
        ls[i] = (u32)__bfloat16_as_ushort(l);
    }
    H = make_uint2(hs[0] | (hs[1] << 16), hs[2] | (hs[3] << 16));
    L = make_uint2(ls[0] | (ls[1] << 16), ls[2] | (ls[3] << 16));
}

__device__ __forceinline__ void ldg_tile(const float* __restrict__ base, int rowMax,
                                         int r0, int tid, float4 r[4]) {
#pragma unroll
    for (int i = 0; i < 4; i++) {
        int c = i * 256 + tid;
        int row = c >> 3, col4 = c & 7;
        int m = r0 + row;
        if (m < rowMax)
            r[i] = *reinterpret_cast<const float4*>(base + (size_t)m * Hh + col4 * 4);
        else
            r[i] = make_float4(0.f, 0.f, 0.f, 0.f);
    }
}
__device__ __forceinline__ void st_tile(char* hi, char* lo, int tid, const float4 r[4]) {
#pragma unroll
    for (int i = 0; i < 4; i++) {
        int c = i * 256 + tid;
        int row = c >> 3, col4 = c & 7;
        uint2 H, L;
        cvt4(r[i], H, L);
        int off = row * LDSB + col4 * 8;
        *reinterpret_cast<uint2*>(hi + off) = H;
        *reinterpret_cast<uint2*>(lo + off) = L;
    }
}

// ============ bf16 3-split HMMA GEMM ============
// C[M, Nout] = A[M, 512*nSeg segmented] x B[Nout, 512/seg]^T  (+bias | +deg*bm)
__global__ __launch_bounds__(256, 1)
void mma_gemm(const float* __restrict__ A, const float* __restrict__ B,
              const float* __restrict__ bias, const float* __restrict__ bm,
              const int* __restrict__ deg, float* __restrict__ C,
              int M, int Nout, int nSeg)
{
    extern __shared__ __align__(16) char smem[];
    const int tid = threadIdx.x;
    const int lane = tid & 31, wid = tid >> 5;
    const int wm = wid & 3, wn = wid >> 2;
    const int m0 = blockIdx.x * 128, n0 = blockIdx.y * 128;
    const int NKB = nSeg * 16;
    const bool msg = (nSeg > 1);
    u32 sb = smem_u32(smem);

    float acc[2][8][4];
#pragma unroll
    for (int i = 0; i < 2; i++)
#pragma unroll
        for (int j = 0; j < 8; j++)
#pragma unroll
            for (int k = 0; k < 4; k++) acc[i][j][k] = 0.f;

    float4 rA[4], rB[4];

    // prologue: load + store k-block 0
    ldg_tile(A, M, m0, tid, rA);
    ldg_tile(B, 1 << 30, n0, tid, rB);
    st_tile(smem, smem + ATILE, tid, rA);
    st_tile(smem + 2 * ATILE, smem + 3 * ATILE, tid, rB);
    __syncthreads();

    for (int kb = 0; kb < NKB; kb++) {
        int buf = kb & 1;
        if (kb + 1 < NKB) {
            int kn = kb + 1;
            int tseg = kn >> 4, koff = (kn & 15) * 32;
            ldg_tile(A + (size_t)tseg * ((size_t)Nn * Hh) + koff, M, m0, tid, rA);
            ldg_tile(B + (size_t)tseg * ((size_t)Hh * Hh) + koff, 1 << 30, n0, tid, rB);
        }
        u32 aHi = sb + buf * BUFSZ;
        u32 aLo = aHi + ATILE, bHi = aHi + 2 * ATILE, bLo = aHi + 3 * ATILE;
#pragma unroll
        for (int ks = 0; ks < 2; ks++) {
            u32 ah[2][4], al[2][4];
#pragma unroll
            for (int mt = 0; mt < 2; mt++) {
                u32 ro = (u32)((wm * 32 + mt * 16 + (lane & 15)) * LDSB
                               + (ks * 16 + (lane >> 4) * 8) * 2);
                ldsm4(ah[mt], aHi + ro);
                ldsm4(al[mt], aLo + ro);
            }
#pragma unroll
            for (int half = 0; half < 2; half++) {
                u32 bh[2][4], bl[2][4];
#pragma unroll
                for (int np = 0; np < 2; np++) {
                    int np2 = half * 2 + np;
                    u32 ro = (u32)((wn * 64 + np2 * 16 + (lane & 7) + ((lane >> 3) & 1) * 8) * LDSB
                                   + (ks * 16 + (lane >> 4) * 8) * 2);
                    ldsm4(bh[np], bHi + ro);
                    ldsm4(bl[np], bLo + ro);
                }
#pragma unroll
                for (int mt = 0; mt < 2; mt++)
#pragma unroll
                    for (int j = 0; j < 4; j++) {
                        int np = j >> 1, sub = j & 1;
                        int nt = half * 4 + j;
                        mma16816(acc[mt][nt], ah[mt], bh[np][sub], bh[np][sub + 2]);
                        mma16816(acc[mt][nt], ah[mt], bl[np][sub], bl[np][sub + 2]);
                        mma16816(acc[mt][nt], al[mt], bh[np][sub], bh[np][sub + 2]);
                    }
            }
        }
        if (kb + 1 < NKB) {
            char* dst = smem + ((kb + 1) & 1) * BUFSZ;
            st_tile(dst, dst + ATILE, tid, rA);
            st_tile(dst + 2 * ATILE, dst + 3 * ATILE, tid, rB);
        }
        __syncthreads();
    }

    // ---- epilogue ----
#pragma unroll
    for (int mt = 0; mt < 2; mt++) {
        int rbase = m0 + wm * 32 + mt * 16 + (lane >> 2);
#pragma unroll
        for (int half = 0; half < 2; half++) {
            int r = rbase + half * 8;
            if (r >= M) continue;
            float dgv[Tt];
            if (msg) {
#pragma unroll
                for (int t = 0; t < Tt; t++) dgv[t] = (float)deg[t * Nn + r];
            }
#pragma unroll
            for (int nt = 0; nt < 8; nt++) {
                int col = n0 + wn * 64 + nt * 8 + (lane & 3) * 2;
                float v0 = acc[mt][nt][half * 2 + 0];
                float v1 = acc[mt][nt][half * 2 + 1];
                if (msg) {
#pragma unroll
                    for (int t = 0; t < Tt; t++) {
                        float2 b = *reinterpret_cast<const float2*>(bm + t * Hh + col);
                        v0 += dgv[t] * b.x;
                        v1 += dgv[t] * b.y;
                    }
                } else {
                    float2 b = *reinterpret_cast<const float2*>(bias + col);
                    v0 += b.x; v1 += b.y;
                }
                *reinterpret_cast<float2*>(C + (size_t)r * Nout + col) = make_float2(v0, v1);
            }
        }
    }
}

// ---------------- utility kernels ----------------
__global__ void zero_f4(float4* p, int n4) {
    int i = blockIdx.x * blockDim.x + threadIdx.x;
    int stride = gridDim.x * blockDim.x;
    float4 z = make_float4(0.f, 0.f, 0.f, 0.f);
    for (; i < n4; i += stride) p[i] = z;
}
__global__ void copy_f4(const float4* __restrict__ s, float4* __restrict__ d, int n4) {
    int i = blockIdx.x * blockDim.x + threadIdx.x;
    int stride = gridDim.x * blockDim.x;
    for (; i < n4; i += stride) d[i] = s[i];
}
__global__ void zero_i(int* p, int n) {
    int i = blockIdx.x * blockDim.x + threadIdx.x;
    if (i < n) p[i] = 0;
}
__global__ void count_deg(const int* __restrict__ edges, int* __restrict__ deg) {
    int idx = blockIdx.x * blockDim.x + threadIdx.x;
    if (idx < Tt * Ee) {
        int t = idx / Ee;
        int tgt = edges[idx * 2 + 1];
        atomicAdd(&deg[t * Nn + tgt], 1);
    }
}

// ---------------- aggregation ----------------
__global__ void aggregate_kernel(const float* __restrict__ h,
                                 const int* __restrict__ edges,
                                 float* __restrict__ S) {
    int warp = (blockIdx.x * blockDim.x + threadIdx.x) >> 5;
    int lane = threadIdx.x & 31;
    if (warp >= Tt * Ee) return;
    int t   = warp / Ee;
    int src = edges[warp * 2 + 0];
    int tgt = edges[warp * 2 + 1];
    const float4* srow = reinterpret_cast<const float4*>(h + (size_t)src * Hh);
    float* drow = S + ((size_t)t * Nn + tgt) * Hh;
#pragma unroll
    for (int i = 0; i < 4; i++) {
        float4 v = srow[i * 32 + lane];
        float* dst = drow + (i * 32 + lane) * 4;
        asm volatile("red.global.add.v4.f32 [%0], {%1, %2, %3, %4};"
                     :: "l"(dst), "f"(v.x), "f"(v.y), "f"(v.z), "f"(v.w)
                     : "memory");
    }
}

// ---------------- GRU elementwise ----------------
__global__ void gru_kernel(const float* __restrict__ gi, const float* __restrict__ gh,
                           const float* __restrict__ h, float* __restrict__ hout) {
    int idx = blockIdx.x * blockDim.x + threadIdx.x;
    if (idx >= Nn * Hh) return;
    int n = idx / Hh;
    int j = idx - n * Hh;
    size_t base = (size_t)n * G3 + j;
    float ir = gi[base],          hr = gh[base];
    float iz = gi[base + Hh],     hz = gh[base + Hh];
    float in_ = gi[base + 2*Hh],  hn = gh[base + 2*Hh];
    float r = 1.f / (1.f + expf(-(ir + hr)));
    float z = 1.f / (1.f + expf(-(iz + hz)));
    float nv = tanhf(in_ + r * hn);
    hout[idx] = (1.f - z) * nv + z * h[idx];
}

// ---------------- column max ----------------
__global__ void pmax_kernel(const float* __restrict__ X, float* __restrict__ pm) {
    int k = threadIdx.x;
    int b = blockIdx.x;
    float m = -INFINITY;
    int r0 = b * 100;
    for (int r = 0; r < 100; r++)
        m = fmaxf(m, X[(size_t)(r0 + r) * Hh + k]);
    pm[b * Hh + k] = m;
}
__global__ void fmax_kernel(const float* __restrict__ pm, float* __restrict__ out) {
    int k = threadIdx.x;
    float m = -INFINITY;
    for (int b = 0; b < 100; b++)
        m = fmaxf(m, pm[b * Hh + k]);
    out[k] = m;
}

// ---------------- launch ----------------
extern "C" void kernel_launch(void* const* d_in, const int* in_sizes, int n_in,
                              void* d_out, int out_size) {
    const float* x     = (const float*)d_in[0];
    const int*   edges = (const int*)  d_in[1];
    const float* W_msg = (const float*)d_in[2];
    const float* b_msg = (const float*)d_in[3];
    const float* W_ih  = (const float*)d_in[4];
    const float* W_hh  = (const float*)d_in[5];
    const float* b_ih  = (const float*)d_in[6];
    const float* b_hh  = (const float*)d_in[7];
    const float* fc_W  = (const float*)d_in[8];
    const float* fc_b  = (const float*)d_in[9];
    float* out = (float*)d_out;

    float *pS, *ph, *pinc, *pgi, *pgh, *ppm;
    int* pdeg;
    cudaGetSymbolAddress((void**)&pS,   g_S);
    cudaGetSymbolAddress((void**)&ph,   g_h);
    cudaGetSymbolAddress((void**)&pinc, g_inc);
    cudaGetSymbolAddress((void**)&pgi,  g_gi);
    cudaGetSymbolAddress((void**)&pgh,  g_gh);
    cudaGetSymbolAddress((void**)&ppm,  g_pm);
    cudaGetSymbolAddress((void**)&pdeg, g_deg);

    cudaFuncSetAttribute(mma_gemm, cudaFuncAttributeMaxDynamicSharedMemorySize, SMEM_BYTES);

    float* hc = ph;
    float* hn = ph + (size_t)Nn * Hh;

    copy_f4<<<2048, 256>>>((const float4*)x, (float4*)hc, Nn * Hh / 4);
    zero_i<<<(Tt * Nn + 255) / 256, 256>>>(pdeg, Tt * Nn);
    count_deg<<<(Tt * Ee + 255) / 256, 256>>>(edges, pdeg);

    dim3 gm((Nn + 127) / 128, Hh / 128);    // 79 x 4
    dim3 gg((Nn + 127) / 128, G3 / 128);    // 79 x 12

    for (int layer = 0; layer < Ll; layer++) {
        const float* Wm_l  = W_msg + (size_t)layer * Tt * Hh * Hh;
        const float* bm_l  = b_msg + (size_t)layer * Tt * Hh;
        const float* Wih_l = W_ih  + (size_t)layer * G3 * Hh;
        const float* Whh_l = W_hh  + (size_t)layer * G3 * Hh;
        const float* bih_l = b_ih  + (size_t)layer * G3;
        const float* bhh_l = b_hh  + (size_t)layer * G3;
        for (int s = 0; s < 2; s++) {
            zero_f4<<<4096, 256>>>((float4*)pS, Tt * Nn * Hh / 4);
            aggregate_kernel<<<(Tt * Ee * 32 + 255) / 256, 256>>>(hc, edges, pS);
            mma_gemm<<<gm, 256, SMEM_BYTES>>>(pS, Wm_l, nullptr, bm_l, pdeg, pinc, Nn, Hh, Tt);
            mma_gemm<<<gg, 256, SMEM_BYTES>>>(pinc, Wih_l, bih_l, nullptr, nullptr, pgi, Nn, G3, 1);
            mma_gemm<<<gg, 256, SMEM_BYTES>>>(hc,   Whh_l, bhh_l, nullptr, nullptr, pgh, Nn, G3, 1);
            gru_kernel<<<(Nn * Hh + 255) / 256, 256>>>(pgi, pgh, hc, hn);
            float* t = hc; hc = hn; hn = t;
        }
    }

    mma_gemm<<<gm, 256, SMEM_BYTES>>>(hc, fc_W, fc_b, nullptr, nullptr, pgi, Nn, Hh, 1);
    pmax_kernel<<<100, 512>>>(pgi, ppm);
    fmax_kernel<<<1, 512>>>(ppm, out);
}

// round 5
// speedup vs baseline: 2.7395x; 1.2265x over previous
#include <cuda_runtime.h>
#include <cuda_bf16.h>
#include <math.h>

#define Nn 10000
#define Hh 512
#define Tt 4
#define Ee 40000
#define Ll 2
#define G3 (3*Hh)
#define TN (Tt*Nn)

typedef unsigned long long u64;
typedef unsigned int u32;

// ---------------- device scratch ----------------
__device__ __align__(16) float g_S  [(size_t)Tt*Nn*Hh];
__device__ __align__(16) float g_h  [2*(size_t)Nn*Hh];
__device__ __align__(16) float g_inc[(size_t)Nn*Hh];
__device__ __align__(16) float g_gi [(size_t)Nn*G3];
__device__ __align__(16) float g_gh [(size_t)Nn*G3];
__device__ __align__(16) float g_pm [100*Hh];
__device__ int g_deg [TN];
__device__ int g_off [TN + 1];
__device__ int g_cur [TN];
__device__ int g_csr [Tt*Ee];
__device__ int g_bsum[64];
__device__ int g_bofs[64];

// ---------------- smem geometry ----------------
#define LDSB  80
#define ATILE 10240
#define BUFSZ (4*ATILE)
#define SMEM_BYTES (2*BUFSZ)

__device__ __forceinline__ u32 smem_u32(const void* p) {
    u32 a;
    asm("{ .reg .u64 t; cvta.to.shared.u64 t, %1; cvt.u32.u64 %0, t; }" : "=r"(a) : "l"(p));
    return a;
}
__device__ __forceinline__ void ldsm4(u32 r[4], u32 addr) {
    asm volatile("ldmatrix.sync.aligned.m8n8.x4.shared.b16 {%0,%1,%2,%3}, [%4];"
                 : "=r"(r[0]), "=r"(r[1]), "=r"(r[2]), "=r"(r[3]) : "r"(addr));
}
__device__ __forceinline__ void mma16816(float d[4], const u32 a[4], u32 b0, u32 b1) {
    asm volatile("mma.sync.aligned.m16n8k16.row.col.f32.bf16.bf16.f32 "
                 "{%0,%1,%2,%3}, {%4,%5,%6,%7}, {%8,%9}, {%0,%1,%2,%3};"
                 : "+f"(d[0]), "+f"(d[1]), "+f"(d[2]), "+f"(d[3])
                 : "r"(a[0]), "r"(a[1]), "r"(a[2]), "r"(a[3]), "r"(b0), "r"(b1));
}
__device__ __forceinline__ void cvt4(float4 f, uint2& H, uint2& L) {
    float v[4] = {f.x, f.y, f.z, f.w};
    u32 hs[4], ls[4];
#pragma unroll
    for (int i = 0; i < 4; i++) {
        __nv_bfloat16 h = __float2bfloat16(v[i]);
        __nv_bfloat16 l = __float2bfloat16(v[i] - __bfloat162float(h));
        hs[i] = (u32)__bfloat16_as_ushort(h);
        ls[i] = (u32)__bfloat16_as_ushort(l);
    }
    H = make_uint2(hs[0] | (hs[1] << 16), hs[2] | (hs[3] << 16));
    L = make_uint2(ls[0] | (ls[1] << 16), ls[2] | (ls[3] << 16));
}

__device__ __forceinline__ void ldg_tile(const float* __restrict__ base, int rowMax,
                                         int r0, int tid, float4 r[4]) {
#pragma unroll
    for (int i = 0; i < 4; i++) {
        int c = i * 256 + tid;
        int row = c >> 3, col4 = c & 7;
        int m = r0 + row;
        if (m < rowMax)
            r[i] = *reinterpret_cast<const float4*>(base + (size_t)m * Hh + col4 * 4);
        else
            r[i] = make_float4(0.f, 0.f, 0.f, 0.f);
    }
}
__device__ __forceinline__ void st_tile(char* hi, char* lo, int tid, const float4 r[4]) {
#pragma unroll
    for (int i = 0; i < 4; i++) {
        int c = i * 256 + tid;
        int row = c >> 3, col4 = c & 7;
        uint2 H, L;
        cvt4(r[i], H, L);
        int off = row * LDSB + col4 * 8;
        *reinterpret_cast<uint2*>(hi + off) = H;
        *reinterpret_cast<uint2*>(lo + off) = L;
    }
}

// ============ bf16 3-split HMMA GEMM (2 CTAs/SM) ============
__global__ __launch_bounds__(256, 2)
void mma_gemm(const float* __restrict__ A, const float* __restrict__ B,
              const float* __restrict__ bias, const float* __restrict__ bm,
              const int* __restrict__ deg, float* __restrict__ C,
              int M, int Nout, int nSeg)
{
    extern __shared__ __align__(16) char smem[];
    const int tid = threadIdx.x;
    const int lane = tid & 31, wid = tid >> 5;
    const int wm = wid & 3, wn = wid >> 2;
    const int m0 = blockIdx.x * 128, n0 = blockIdx.y * 128;
    const int NKB = nSeg * 16;
    const bool msg = (nSeg > 1);
    u32 sb = smem_u32(smem);

    float acc[2][8][4];
#pragma unroll
    for (int i = 0; i < 2; i++)
#pragma unroll
        for (int j = 0; j < 8; j++)
#pragma unroll
            for (int k = 0; k < 4; k++) acc[i][j][k] = 0.f;

    // prologue: k-block 0 into buffer 0
    {
        float4 rA[4], rB[4];
        ldg_tile(A, M, m0, tid, rA);
        ldg_tile(B, 1 << 30, n0, tid, rB);
        st_tile(smem, smem + ATILE, tid, rA);
        st_tile(smem + 2 * ATILE, smem + 3 * ATILE, tid, rB);
    }
    __syncthreads();

    for (int kb = 0; kb < NKB; kb++) {
        int buf = kb & 1;
        // prefetch + store next k-block into the other buffer (short reg live range)
        if (kb + 1 < NKB) {
            float4 rA[4], rB[4];
            int kn = kb + 1;
            int tseg = kn >> 4, koff = (kn & 15) * 32;
            ldg_tile(A + (size_t)tseg * ((size_t)Nn * Hh) + koff, M, m0, tid, rA);
            ldg_tile(B + (size_t)tseg * ((size_t)Hh * Hh) + koff, 1 << 30, n0, tid, rB);
            char* dst = smem + (kn & 1) * BUFSZ;
            st_tile(dst, dst + ATILE, tid, rA);
            st_tile(dst + 2 * ATILE, dst + 3 * ATILE, tid, rB);
        }
        u32 aHi = sb + buf * BUFSZ;
        u32 aLo = aHi + ATILE, bHi = aHi + 2 * ATILE, bLo = aHi + 3 * ATILE;
#pragma unroll
        for (int ks = 0; ks < 2; ks++) {
            u32 ah[2][4], al[2][4];
#pragma unroll
            for (int mt = 0; mt < 2; mt++) {
                u32 ro = (u32)((wm * 32 + mt * 16 + (lane & 15)) * LDSB
                               + (ks * 16 + (lane >> 4) * 8) * 2);
                ldsm4(ah[mt], aHi + ro);
                ldsm4(al[mt], aLo + ro);
            }
#pragma unroll
            for (int half = 0; half < 2; half++) {
                u32 bh[2][4], bl[2][4];
#pragma unroll
                for (int np = 0; np < 2; np++) {
                    int np2 = half * 2 + np;
                    u32 ro = (u32)((wn * 64 + np2 * 16 + (lane & 7) + ((lane >> 3) & 1) * 8) * LDSB
                                   + (ks * 16 + (lane >> 4) * 8) * 2);
                    ldsm4(bh[np], bHi + ro);
                    ldsm4(bl[np], bLo + ro);
                }
#pragma unroll
                for (int mt = 0; mt < 2; mt++)
#pragma unroll
                    for (int j = 0; j < 4; j++) {
                        int np = j >> 1, sub = j & 1;
                        int nt = half * 4 + j;
                        mma16816(acc[mt][nt], ah[mt], bh[np][sub], bh[np][sub + 2]);
                        mma16816(acc[mt][nt], ah[mt], bl[np][sub], bl[np][sub + 2]);
                        mma16816(acc[mt][nt], al[mt], bh[np][sub], bh[np][sub + 2]);
                    }
            }
        }
        __syncthreads();
    }

    // ---- epilogue ----
#pragma unroll
    for (int mt = 0; mt < 2; mt++) {
        int rbase = m0 + wm * 32 + mt * 16 + (lane >> 2);
#pragma unroll
        for (int half = 0; half < 2; half++) {
            int r = rbase + half * 8;
            if (r >= M) continue;
            float dgv[Tt];
            if (msg) {
#pragma unroll
                for (int t = 0; t < Tt; t++) dgv[t] = (float)deg[t * Nn + r];
            }
#pragma unroll
            for (int nt = 0; nt < 8; nt++) {
                int col = n0 + wn * 64 + nt * 8 + (lane & 3) * 2;
                float v0 = acc[mt][nt][half * 2 + 0];
                float v1 = acc[mt][nt][half * 2 + 1];
                if (msg) {
#pragma unroll
                    for (int t = 0; t < Tt; t++) {
                        float2 b = *reinterpret_cast<const float2*>(bm + t * Hh + col);
                        v0 += dgv[t] * b.x;
                        v1 += dgv[t] * b.y;
                    }
                } else {
                    float2 b = *reinterpret_cast<const float2*>(bias + col);
                    v0 += b.x; v1 += b.y;
                }
                *reinterpret_cast<float2*>(C + (size_t)r * Nout + col) = make_float2(v0, v1);
            }
        }
    }
}

// ---------------- utility kernels ----------------
__global__ void copy_f4(const float4* __restrict__ s, float4* __restrict__ d, int n4) {
    int i = blockIdx.x * blockDim.x + threadIdx.x;
    int stride = gridDim.x * blockDim.x;
    for (; i < n4; i += stride) d[i] = s[i];
}
__global__ void zero_i(int* p, int n) {
    int i = blockIdx.x * blockDim.x + threadIdx.x;
    if (i < n) p[i] = 0;
}
__global__ void count_deg(const int* __restrict__ edges, int* __restrict__ deg) {
    int idx = blockIdx.x * blockDim.x + threadIdx.x;
    if (idx < Tt * Ee) {
        int t = idx / Ee;
        int tgt = edges[idx * 2 + 1];
        atomicAdd(&deg[t * Nn + tgt], 1);
    }
}

// ---------------- CSR build (once per launch; edges are constant) ----------------
__global__ void scan1(const int* __restrict__ deg, int* __restrict__ off, int* __restrict__ bsum) {
    __shared__ int sm[1024];
    int t = threadIdx.x;
    int i = blockIdx.x * 1024 + t;
    int v = (i < TN) ? deg[i] : 0;
    sm[t] = v;
    __syncthreads();
    for (int d = 1; d < 1024; d <<= 1) {
        int x = (t >= d) ? sm[t - d] : 0;
        __syncthreads();
        sm[t] += x;
        __syncthreads();
    }
    if (i < TN) off[i + 1] = sm[t];
    if (t == 1023) bsum[blockIdx.x] = sm[t];
}
__global__ void scan2(const int* __restrict__ bsum, int* __restrict__ bofs, int nb) {
    __shared__ int sm[64];
    int t = threadIdx.x;
    int v = (t < nb) ? bsum[t] : 0;
    sm[t] = v;
    __syncthreads();
    for (int d = 1; d < 64; d <<= 1) {
        int x = (t >= d) ? sm[t - d] : 0;
        __syncthreads();
        sm[t] += x;
        __syncthreads();
    }
    bofs[t] = sm[t] - v;   // exclusive
}
__global__ void scan3(int* __restrict__ off, const int* __restrict__ bofs) {
    int i = blockIdx.x * blockDim.x + threadIdx.x;
    if (i == 0) off[0] = 0;
    if (i < TN) off[i + 1] += bofs[i >> 10];
}
__global__ void scatter_csr(const int* __restrict__ edges, const int* __restrict__ off,
                            int* __restrict__ cur, int* __restrict__ csr) {
    int idx = blockIdx.x * blockDim.x + threadIdx.x;
    if (idx >= Tt * Ee) return;
    int t = idx / Ee;
    int src = edges[idx * 2 + 0];
    int tgt = edges[idx * 2 + 1];
    int r = t * Nn + tgt;
    int p = off[r] + atomicAdd(&cur[r], 1);
    csr[p] = src;
}

// ---------------- CSR aggregation: one warp per (type,node) row, no atomics ----------------
__global__ void agg_csr(const float* __restrict__ h, const int* __restrict__ csr,
                        const int* __restrict__ off, float* __restrict__ S) {
    int row = (blockIdx.x * blockDim.x + threadIdx.x) >> 5;
    int lane = threadIdx.x & 31;
    if (row >= TN) return;
    int s = off[row], e = off[row + 1];
    float4 a0 = make_float4(0.f,0.f,0.f,0.f), a1 = a0, a2 = a0, a3 = a0;
    for (int i = s; i < e; i++) {
        int src = __ldg(csr + i);
        const float4* hp = reinterpret_cast<const float4*>(h + (size_t)src * Hh);
        float4 v0 = hp[lane], v1 = hp[lane + 32], v2 = hp[lane + 64], v3 = hp[lane + 96];
        a0.x += v0.x; a0.y += v0.y; a0.z += v0.z; a0.w += v0.w;
        a1.x += v1.x; a1.y += v1.y; a1.z += v1.z; a1.w += v1.w;
        a2.x += v2.x; a2.y += v2.y; a2.z += v2.z; a2.w += v2.w;
        a3.x += v3.x; a3.y += v3.y; a3.z += v3.z; a3.w += v3.w;
    }
    float4* Sp = reinterpret_cast<float4*>(S + (size_t)row * Hh);
    Sp[lane] = a0; Sp[lane + 32] = a1; Sp[lane + 64] = a2; Sp[lane + 96] = a3;
}

// ---------------- GRU elementwise ----------------
__global__ void gru_kernel(const float* __restrict__ gi, const float* __restrict__ gh,
                           const float* __restrict__ h, float* __restrict__ hout) {
    int idx = blockIdx.x * blockDim.x + threadIdx.x;
    if (idx >= Nn * Hh) return;
    int n = idx / Hh;
    int j = idx - n * Hh;
    size_t base = (size_t)n * G3 + j;
    float ir = gi[base],          hr = gh[base];
    float iz = gi[base + Hh],     hz = gh[base + Hh];
    float in_ = gi[base + 2*Hh],  hn = gh[base + 2*Hh];
    float r = 1.f / (1.f + expf(-(ir + hr)));
    float z = 1.f / (1.f + expf(-(iz + hz)));
    float nv = tanhf(in_ + r * hn);
    hout[idx] = (1.f - z) * nv + z * h[idx];
}

// ---------------- column max ----------------
__global__ void pmax_kernel(const float* __restrict__ X, float* __restrict__ pm) {
    int k = threadIdx.x;
    int b = blockIdx.x;
    float m = -INFINITY;
    int r0 = b * 100;
    for (int r = 0; r < 100; r++)
        m = fmaxf(m, X[(size_t)(r0 + r) * Hh + k]);
    pm[b * Hh + k] = m;
}
__global__ void fmax_kernel(const float* __restrict__ pm, float* __restrict__ out) {
    int k = threadIdx.x;
    float m = -INFINITY;
    for (int b = 0; b < 100; b++)
        m = fmaxf(m, pm[b * Hh + k]);
    out[k] = m;
}

// ---------------- launch ----------------
extern "C" void kernel_launch(void* const* d_in, const int* in_sizes, int n_in,
                              void* d_out, int out_size) {
    const float* x     = (const float*)d_in[0];
    const int*   edges = (const int*)  d_in[1];
    const float* W_msg = (const float*)d_in[2];
    const float* b_msg = (const float*)d_in[3];
    const float* W_ih  = (const float*)d_in[4];
    const float* W_hh  = (const float*)d_in[5];
    const float* b_ih  = (const float*)d_in[6];
    const float* b_hh  = (const float*)d_in[7];
    const float* fc_W  = (const float*)d_in[8];
    const float* fc_b  = (const float*)d_in[9];
    float* out = (float*)d_out;

    float *pS, *ph, *pinc, *pgi, *pgh, *ppm;
    int *pdeg, *poff, *pcur, *pcsr, *pbsum, *pbofs;
    cudaGetSymbolAddress((void**)&pS,    g_S);
    cudaGetSymbolAddress((void**)&ph,    g_h);
    cudaGetSymbolAddress((void**)&pinc,  g_inc);
    cudaGetSymbolAddress((void**)&pgi,   g_gi);
    cudaGetSymbolAddress((void**)&pgh,   g_gh);
    cudaGetSymbolAddress((void**)&ppm,   g_pm);
    cudaGetSymbolAddress((void**)&pdeg,  g_deg);
    cudaGetSymbolAddress((void**)&poff,  g_off);
    cudaGetSymbolAddress((void**)&pcur,  g_cur);
    cudaGetSymbolAddress((void**)&pcsr,  g_csr);
    cudaGetSymbolAddress((void**)&pbsum, g_bsum);
    cudaGetSymbolAddress((void**)&pbofs, g_bofs);

    cudaFuncSetAttribute(mma_gemm, cudaFuncAttributeMaxDynamicSharedMemorySize, SMEM_BYTES);

    float* hc = ph;
    float* hn = ph + (size_t)Nn * Hh;

    copy_f4<<<2048, 256>>>((const float4*)x, (float4*)hc, Nn * Hh / 4);

    // CSR build (edges fixed for whole launch)
    zero_i<<<(TN + 255) / 256, 256>>>(pdeg, TN);
    zero_i<<<(TN + 255) / 256, 256>>>(pcur, TN);
    count_deg<<<(Tt * Ee + 255) / 256, 256>>>(edges, pdeg);
    scan1<<<(TN + 1023) / 1024, 1024>>>(pdeg, poff, pbsum);
    scan2<<<1, 64>>>(pbsum, pbofs, (TN + 1023) / 1024);
    scan3<<<(TN + 255) / 256, 256>>>(poff, pbofs);
    scatter_csr<<<(Tt * Ee + 255) / 256, 256>>>(edges, poff, pcur, pcsr);

    dim3 gm((Nn + 127) / 128, Hh / 128);    // 79 x 4
    dim3 gg((Nn + 127) / 128, G3 / 128);    // 79 x 12
    int aggBlocks = (TN * 32 + 255) / 256;

    for (int layer = 0; layer < Ll; layer++) {
        const float* Wm_l  = W_msg + (size_t)layer * Tt * Hh * Hh;
        const float* bm_l  = b_msg + (size_t)layer * Tt * Hh;
        const float* Wih_l = W_ih  + (size_t)layer * G3 * Hh;
        const float* Whh_l = W_hh  + (size_t)layer * G3 * Hh;
        const float* bih_l = b_ih  + (size_t)layer * G3;
        const float* bhh_l = b_hh  + (size_t)layer * G3;
        for (int s = 0; s < 2; s++) {
            agg_csr<<<aggBlocks, 256>>>(hc, pcsr, poff, pS);
            mma_gemm<<<gm, 256, SMEM_BYTES>>>(pS, Wm_l, nullptr, bm_l, pdeg, pinc, Nn, Hh, Tt);
            mma_gemm<<<gg, 256, SMEM_BYTES>>>(pinc, Wih_l, bih_l, nullptr, nullptr, pgi, Nn, G3, 1);
            mma_gemm<<<gg, 256, SMEM_BYTES>>>(hc,   Whh_l, bhh_l, nullptr, nullptr, pgh, Nn, G3, 1);
            gru_kernel<<<(Nn * Hh + 255) / 256, 256>>>(pgi, pgh, hc, hn);
            float* t = hc; hc = hn; hn = t;
        }
    }

    mma_gemm<<<gm, 256, SMEM_BYTES>>>(hc, fc_W, fc_b, nullptr, nullptr, pgi, Nn, Hh, 1);
    pmax_kernel<<<100, 512>>>(pgi, ppm);
    fmax_kernel<<<1, 512>>>(ppm, out);
}